// round 6
// baseline (speedup 1.0000x reference)
#include <cuda_runtime.h>
#include <mma.h>
#include <math.h>

using namespace nvcuda;

#define NMAX 50000
#define NPAD 50048   // NMAX rounded up to 128 (unguarded wmma tile stores)
#define EMAX 800000
#define GSEG 64
#define STILE 1024

// ---------------- scratch (device globals; zero-initialized at module load) ----------------
__device__ float g_h[NPAD * 128];      // GAT-transformed features (padded)
__device__ float g_asrc[NMAX * 4];
__device__ float g_adst[NMAX * 4];
__device__ float g_out1[NMAX * 128];   // GAT output, pre-scaled by dinv[node]
__device__ float g_h2[NPAD * 128];     // out1 @ W_gcn (padded)
__device__ float g_out2[NMAX * 128];
__device__ float g_dinv[NMAX];
__device__ float g_eg[NMAX];
__device__ int   g_deg[NMAX];
__device__ int   g_rowptr[NMAX + 1];
__device__ int   g_wpos[NMAX];
__device__ int   g_col[EMAX + NMAX];
__device__ int   g_tsum[64];
__device__ int   g_toff[64];

__device__ __forceinline__ float lrelu(float v) { return fmaxf(v, 0.2f * v); }
__device__ __forceinline__ float elu(float v) { return v > 0.f ? v : __expf(v) - 1.f; }

// ---------------- CSR: count degrees ----------------
__global__ void k_count(const int* __restrict__ ei, int E) {
    int i = blockIdx.x * blockDim.x + threadIdx.x;
    if (i < E) atomicAdd(&g_deg[__ldg(ei + E + i)], 1);
}

__global__ void k_scanA(int N) {
    __shared__ int red[8];
    int t = threadIdx.x;
    int i0 = blockIdx.x * STILE + t * 4;
    int s = 0;
#pragma unroll
    for (int j = 0; j < 4; j++) {
        int i = i0 + j;
        if (i < N) s += g_deg[i] + 1;
    }
#pragma unroll
    for (int o = 16; o; o >>= 1) s += __shfl_down_sync(0xffffffffu, s, o);
    if ((t & 31) == 0) red[t >> 5] = s;
    __syncthreads();
    if (t == 0) {
        int tot = 0;
#pragma unroll
        for (int i = 0; i < 8; i++) tot += red[i];
        g_tsum[blockIdx.x] = tot;
    }
}

__global__ void k_scanB(int ntiles, int N) {
    __shared__ int w0sum;
    int t = threadIdx.x;
    int own = (t < ntiles) ? g_tsum[t] : 0;
    int v = own;
#pragma unroll
    for (int o = 1; o < 32; o <<= 1) {
        int u = __shfl_up_sync(0xffffffffu, v, o);
        if ((t & 31) >= o) v += u;
    }
    if (t == 31) w0sum = v;
    __syncthreads();
    if (t >= 32) v += w0sum;
    if (t < ntiles) g_toff[t] = v - own;
    if (t == ntiles - 1) g_rowptr[N] = v;
}

__global__ void k_scanC(int N) {
    __shared__ int sm[256];
    int t = threadIdx.x;
    int i0 = blockIdx.x * STILE + t * 4;
    int v[4], ts = 0;
#pragma unroll
    for (int j = 0; j < 4; j++) {
        int i = i0 + j;
        v[j] = (i < N) ? g_deg[i] + 1 : 0;
        ts += v[j];
    }
    sm[t] = ts;
    __syncthreads();
    for (int o = 1; o < 256; o <<= 1) {
        int x = (t >= o) ? sm[t - o] : 0;
        __syncthreads();
        sm[t] += x;
        __syncthreads();
    }
    int base = g_toff[blockIdx.x] + sm[t] - ts;
#pragma unroll
    for (int j = 0; j < 4; j++) {
        int i = i0 + j;
        if (i < N) {
            g_rowptr[i] = base;
            g_col[base] = i;
            g_wpos[i] = base + 1;
            g_dinv[i] = rsqrtf((float)v[j]);
            base += v[j];
        }
    }
}

__global__ void k_fill(const int* __restrict__ ei, int E) {
    int i = blockIdx.x * blockDim.x + threadIdx.x;
    if (i >= E) return;
    int s = __ldg(ei + i);
    int d = __ldg(ei + E + i);
    int pos = atomicAdd(&g_wpos[d], 1);
    g_col[pos] = s;
}

// ---------------- tensor-core GEMM: C[NPAD,128] = A[N,128] @ B[128,128] ----------------
// tf32 hi/lo split (3 mma products) for fp32-grade precision.
// Block: 128x128 tile, 256 thr = 8 warps (2 row x 4 col), warp tile 64x32.
__global__ __launch_bounds__(256, 2) void gemm_tc(
    const float* __restrict__ A, const float* __restrict__ B,
    float* __restrict__ C, int nrows) {
    __shared__ float sAh[128][20];
    __shared__ float sAl[128][20];
    __shared__ float sBh[16][132];
    __shared__ float sBl[16][132];

    int tid = threadIdx.x;
    int wid = tid >> 5;
    int warp_m = wid & 1;    // 0..1 (64-row group)
    int warp_n = wid >> 1;   // 0..3 (32-col group)
    int row0 = blockIdx.x * 128;

    wmma::fragment<wmma::accumulator, 16, 16, 8, float> acc[4][2];
#pragma unroll
    for (int mt = 0; mt < 4; mt++)
#pragma unroll
        for (int nt = 0; nt < 2; nt++) wmma::fill_fragment(acc[mt][nt], 0.f);

    for (int k0 = 0; k0 < 128; k0 += 16) {
        __syncthreads();
        // fill A tile (128x16) as hi/lo tf32: 512 float4 items, 2 per thread
#pragma unroll
        for (int u = 0; u < 2; u++) {
            int it = tid * 2 + u;
            int r = it >> 2, c = (it & 3) * 4;
            float4 v = make_float4(0.f, 0.f, 0.f, 0.f);
            if (row0 + r < nrows)
                v = *(const float4*)(A + (long long)(row0 + r) * 128 + k0 + c);
            float h0 = wmma::__float_to_tf32(v.x);
            float h1 = wmma::__float_to_tf32(v.y);
            float h2 = wmma::__float_to_tf32(v.z);
            float h3 = wmma::__float_to_tf32(v.w);
            sAh[r][c + 0] = h0; sAl[r][c + 0] = wmma::__float_to_tf32(v.x - h0);
            sAh[r][c + 1] = h1; sAl[r][c + 1] = wmma::__float_to_tf32(v.y - h1);
            sAh[r][c + 2] = h2; sAl[r][c + 2] = wmma::__float_to_tf32(v.z - h2);
            sAh[r][c + 3] = h3; sAl[r][c + 3] = wmma::__float_to_tf32(v.w - h3);
        }
        // fill B tile (16x128): 512 float4 items, 2 per thread
#pragma unroll
        for (int u = 0; u < 2; u++) {
            int it = tid * 2 + u;
            int kr = it >> 5, c = (it & 31) * 4;
            float4 v = *(const float4*)(B + (long long)(k0 + kr) * 128 + c);
            float h0 = wmma::__float_to_tf32(v.x);
            float h1 = wmma::__float_to_tf32(v.y);
            float h2 = wmma::__float_to_tf32(v.z);
            float h3 = wmma::__float_to_tf32(v.w);
            sBh[kr][c + 0] = h0; sBl[kr][c + 0] = wmma::__float_to_tf32(v.x - h0);
            sBh[kr][c + 1] = h1; sBl[kr][c + 1] = wmma::__float_to_tf32(v.y - h1);
            sBh[kr][c + 2] = h2; sBl[kr][c + 2] = wmma::__float_to_tf32(v.z - h2);
            sBh[kr][c + 3] = h3; sBl[kr][c + 3] = wmma::__float_to_tf32(v.w - h3);
        }
        __syncthreads();

#pragma unroll
        for (int ks = 0; ks < 16; ks += 8) {
            wmma::fragment<wmma::matrix_a, 16, 16, 8, wmma::precision::tf32, wmma::row_major> ah[4], al[4];
            wmma::fragment<wmma::matrix_b, 16, 16, 8, wmma::precision::tf32, wmma::row_major> bh[2], bl[2];
#pragma unroll
            for (int mt = 0; mt < 4; mt++) {
                int r = warp_m * 64 + mt * 16;
                wmma::load_matrix_sync(ah[mt], &sAh[r][ks], 20);
                wmma::load_matrix_sync(al[mt], &sAl[r][ks], 20);
            }
#pragma unroll
            for (int nt = 0; nt < 2; nt++) {
                int c = warp_n * 32 + nt * 16;
                wmma::load_matrix_sync(bh[nt], &sBh[ks][c], 132);
                wmma::load_matrix_sync(bl[nt], &sBl[ks][c], 132);
            }
#pragma unroll
            for (int mt = 0; mt < 4; mt++)
#pragma unroll
                for (int nt = 0; nt < 2; nt++) {
                    wmma::mma_sync(acc[mt][nt], ah[mt], bh[nt], acc[mt][nt]);
                    wmma::mma_sync(acc[mt][nt], ah[mt], bl[nt], acc[mt][nt]);
                    wmma::mma_sync(acc[mt][nt], al[mt], bh[nt], acc[mt][nt]);
                }
        }
    }

    // store (C padded to NPAD rows, unguarded)
#pragma unroll
    for (int mt = 0; mt < 4; mt++) {
#pragma unroll
        for (int nt = 0; nt < 2; nt++) {
            int r = row0 + warp_m * 64 + mt * 16;
            int c = warp_n * 32 + nt * 16;
            wmma::store_matrix_sync(C + (long long)r * 128 + c, acc[mt][nt],
                                    128, wmma::mem_row_major);
        }
    }
}

// ---------------- attention logits per node/head ----------------
__global__ void k_attn(const float* __restrict__ att_src,
                       const float* __restrict__ att_dst, int N) {
    int t = blockIdx.x * blockDim.x + threadIdx.x;
    if (t >= N * 4) return;
    int n = t >> 2, hd = t & 3;
    const float* hp = g_h + (long long)n * 128 + hd * 32;
    float s1 = 0.f, s2 = 0.f;
#pragma unroll
    for (int c = 0; c < 32; c += 4) {
        float4 hv = *(const float4*)(hp + c);
        float4 as = *(const float4*)(att_src + hd * 32 + c);
        float4 ad = *(const float4*)(att_dst + hd * 32 + c);
        s1 += hv.x * as.x + hv.y * as.y + hv.z * as.z + hv.w * as.w;
        s2 += hv.x * ad.x + hv.y * ad.y + hv.z * ad.z + hv.w * ad.w;
    }
    g_asrc[t] = s1;
    g_adst[t] = s2;
}

// ---------------- GAT aggregation: warp per dst node; out1 pre-scaled by dinv ----------------
__global__ void k_gat_agg(const float* __restrict__ b_gat,
                          const float* __restrict__ bn_w,
                          const float* __restrict__ bn_b, int N) {
    int t = blockIdx.x * blockDim.x + threadIdx.x;
    int node = t >> 5, lane = t & 31;
    if (node >= N) return;
    int head = lane >> 3;
    int beg = g_rowptr[node], end = g_rowptr[node + 1];
    float adh = g_adst[node * 4 + head];

    float4 acc = make_float4(0.f, 0.f, 0.f, 0.f);
    float den = 0.f;
    int i = beg;
    for (; i + 4 <= end; i += 4) {
        int s0 = __ldg(&g_col[i + 0]);
        int s1 = __ldg(&g_col[i + 1]);
        int s2 = __ldg(&g_col[i + 2]);
        int s3 = __ldg(&g_col[i + 3]);
        float a0 = __ldg(&g_asrc[s0 * 4 + head]);
        float a1 = __ldg(&g_asrc[s1 * 4 + head]);
        float a2 = __ldg(&g_asrc[s2 * 4 + head]);
        float a3 = __ldg(&g_asrc[s3 * 4 + head]);
        float4 h0 = *(const float4*)(g_h + (long long)s0 * 128 + lane * 4);
        float4 h1 = *(const float4*)(g_h + (long long)s1 * 128 + lane * 4);
        float4 h2 = *(const float4*)(g_h + (long long)s2 * 128 + lane * 4);
        float4 h3 = *(const float4*)(g_h + (long long)s3 * 128 + lane * 4);
        float e0 = __expf(lrelu(a0 + adh));
        float e1 = __expf(lrelu(a1 + adh));
        float e2 = __expf(lrelu(a2 + adh));
        float e3 = __expf(lrelu(a3 + adh));
        den += (e0 + e1) + (e2 + e3);
        acc.x += e0 * h0.x + e1 * h1.x + e2 * h2.x + e3 * h3.x;
        acc.y += e0 * h0.y + e1 * h1.y + e2 * h2.y + e3 * h3.y;
        acc.z += e0 * h0.z + e1 * h1.z + e2 * h2.z + e3 * h3.z;
        acc.w += e0 * h0.w + e1 * h1.w + e2 * h2.w + e3 * h3.w;
    }
    for (; i < end; i++) {
        int s = __ldg(&g_col[i]);
        float a = __ldg(&g_asrc[s * 4 + head]);
        float e = __expf(lrelu(a + adh));
        den += e;
        float4 hv = *(const float4*)(g_h + (long long)s * 128 + lane * 4);
        acc.x += e * hv.x; acc.y += e * hv.y;
        acc.z += e * hv.z; acc.w += e * hv.w;
    }
    float inv = 1.f / (den + 1e-16f);
    float dd = g_dinv[node];   // GCN src-side normalization folded in
    int c4 = lane * 4;
    float4 bg = *(const float4*)(b_gat + c4);
    float4 wv = *(const float4*)(bn_w + c4);
    float4 bv = *(const float4*)(bn_b + c4);
    acc.x = (elu(acc.x * inv + bg.x) * wv.x + bv.x) * dd;
    acc.y = (elu(acc.y * inv + bg.y) * wv.y + bv.y) * dd;
    acc.z = (elu(acc.z * inv + bg.z) * wv.z + bv.z) * dd;
    acc.w = (elu(acc.w * inv + bg.w) * wv.w + bv.w) * dd;
    *(float4*)(g_out1 + (long long)node * 128 + c4) = acc;
}

// ---------------- GCN aggregation + post + gate (dinv[src] pre-folded into out1) ----------------
__global__ void k_gcn_agg(const float* __restrict__ b_gcn,
                          const float* __restrict__ bn_w,
                          const float* __restrict__ bn_b,
                          const float* __restrict__ W_gate,
                          const float* __restrict__ b_gate, int N) {
    int t = blockIdx.x * blockDim.x + threadIdx.x;
    int node = t >> 5, lane = t & 31;
    if (node >= N) return;
    int beg = g_rowptr[node], end = g_rowptr[node + 1];

    float4 acc = make_float4(0.f, 0.f, 0.f, 0.f);
    int i = beg;
    for (; i + 4 <= end; i += 4) {
        int s0 = __ldg(&g_col[i + 0]);
        int s1 = __ldg(&g_col[i + 1]);
        int s2 = __ldg(&g_col[i + 2]);
        int s3 = __ldg(&g_col[i + 3]);
        float4 h0 = *(const float4*)(g_h2 + (long long)s0 * 128 + lane * 4);
        float4 h1 = *(const float4*)(g_h2 + (long long)s1 * 128 + lane * 4);
        float4 h2 = *(const float4*)(g_h2 + (long long)s2 * 128 + lane * 4);
        float4 h3 = *(const float4*)(g_h2 + (long long)s3 * 128 + lane * 4);
        acc.x += (h0.x + h1.x) + (h2.x + h3.x);
        acc.y += (h0.y + h1.y) + (h2.y + h3.y);
        acc.z += (h0.z + h1.z) + (h2.z + h3.z);
        acc.w += (h0.w + h1.w) + (h2.w + h3.w);
    }
    for (; i < end; i++) {
        int s = __ldg(&g_col[i]);
        float4 hv = *(const float4*)(g_h2 + (long long)s * 128 + lane * 4);
        acc.x += hv.x; acc.y += hv.y; acc.z += hv.z; acc.w += hv.w;
    }
    float dd = g_dinv[node];
    int c4 = lane * 4;
    float4 bg = *(const float4*)(b_gcn + c4);
    float4 wv = *(const float4*)(bn_w + c4);
    float4 bv = *(const float4*)(bn_b + c4);
    acc.x = elu(acc.x * dd + bg.x) * wv.x + bv.x;
    acc.y = elu(acc.y * dd + bg.y) * wv.y + bv.y;
    acc.z = elu(acc.z * dd + bg.z) * wv.z + bv.z;
    acc.w = elu(acc.w * dd + bg.w) * wv.w + bv.w;
    *(float4*)(g_out2 + (long long)node * 128 + c4) = acc;

    float4 wg = *(const float4*)(W_gate + c4);
    float p = acc.x * wg.x + acc.y * wg.y + acc.z * wg.z + acc.w * wg.w;
#pragma unroll
    for (int o = 16; o; o >>= 1) p += __shfl_xor_sync(0xffffffffu, p, o);
    if (lane == 0) g_eg[node] = __expf(p + b_gate[0]);
}

__device__ __forceinline__ int lower_bound(const int* __restrict__ batch, int N, int key) {
    int lo = 0, hi = N;
    while (lo < hi) {
        int mid = (lo + hi) >> 1;
        if (__ldg(batch + mid) < key) lo = mid + 1; else hi = mid;
    }
    return lo;
}

// ---------------- pooling + final FC fused; tail re-zeroes g_deg ----------------
__global__ void k_pool_final(const int* __restrict__ batch,
                             const float* __restrict__ W_fc,
                             const float* __restrict__ b_fc,
                             float* __restrict__ out, int N) {
    __shared__ float red[8];
    __shared__ float s_acc[256];
    __shared__ float s_inv;
    int gph = blockIdx.x;
    int t = threadIdx.x;
    int lane = t & 31, wrp = t >> 5;
    int beg = lower_bound(batch, N, gph);
    int end = lower_bound(batch, N, gph + 1);

    float s = 0.f;
    for (int n = beg + t; n < end; n += 256) s += g_eg[n];
#pragma unroll
    for (int o = 16; o; o >>= 1) s += __shfl_xor_sync(0xffffffffu, s, o);
    if (lane == 0) red[wrp] = s;
    __syncthreads();
    if (t == 0) {
        float tot = 0.f;
#pragma unroll
        for (int i = 0; i < 8; i++) tot += red[i];
        s_inv = 1.f / (tot + 1e-16f);
    }
    __syncthreads();
    float inv = s_inv;

    int half = t >> 7, c = t & 127;
    float acc = 0.f;
    int n = beg + half;
    for (; n + 8 <= end; n += 8) {
        acc += g_eg[n + 0] * g_out2[(long long)(n + 0) * 128 + c];
        acc += g_eg[n + 2] * g_out2[(long long)(n + 2) * 128 + c];
        acc += g_eg[n + 4] * g_out2[(long long)(n + 4) * 128 + c];
        acc += g_eg[n + 6] * g_out2[(long long)(n + 6) * 128 + c];
    }
    for (; n < end; n += 2)
        acc += g_eg[n] * g_out2[(long long)n * 128 + c];
    s_acc[t] = acc;
    __syncthreads();

    if (t < 128) {
        float p = (s_acc[t] + s_acc[t + 128]) * inv * W_fc[t];
#pragma unroll
        for (int o = 16; o; o >>= 1) p += __shfl_xor_sync(0xffffffffu, p, o);
        if (lane == 0) red[wrp] = p;
    }
    __syncthreads();
    if (t == 0) out[gph] = red[0] + red[1] + red[2] + red[3] + b_fc[0];

    int gid = gph * 256 + t;
    for (int k = gid; k < NMAX; k += GSEG * 256) g_deg[k] = 0;
}

extern "C" void kernel_launch(void* const* d_in, const int* in_sizes, int n_in,
                              void* d_out, int out_size) {
    const float* x       = (const float*)d_in[0];
    const int*   ei      = (const int*)d_in[1];
    const int*   batch   = (const int*)d_in[2];
    const float* W_gat   = (const float*)d_in[3];
    const float* att_src = (const float*)d_in[4];
    const float* att_dst = (const float*)d_in[5];
    const float* b_gat   = (const float*)d_in[6];
    const float* bn1_w   = (const float*)d_in[7];
    const float* bn1_b   = (const float*)d_in[8];
    const float* W_gcn   = (const float*)d_in[9];
    const float* b_gcn   = (const float*)d_in[10];
    const float* bn2_w   = (const float*)d_in[11];
    const float* bn2_b   = (const float*)d_in[12];
    const float* W_gate  = (const float*)d_in[13];
    const float* b_gate  = (const float*)d_in[14];
    const float* W_fc    = (const float*)d_in[15];
    const float* b_fc    = (const float*)d_in[16];
    float* out = (float*)d_out;

    int N = in_sizes[0] / 128;
    int E = in_sizes[1] / 2;
    if (N > NMAX) N = NMAX;
    if (E > EMAX) E = EMAX;
    int ntiles = (N + STILE - 1) / STILE;

    float *p_h, *p_out1, *p_h2;
    cudaGetSymbolAddress((void**)&p_h, g_h);
    cudaGetSymbolAddress((void**)&p_out1, g_out1);
    cudaGetSymbolAddress((void**)&p_h2, g_h2);

    int gemm_grid = (N + 127) / 128;

    // CSR build — gemm1 is launch #4 (ncu capture slot)
    k_count<<<(E + 255) / 256, 256>>>(ei, E);
    k_scanA<<<ntiles, 256>>>(N);
    k_scanB<<<1, 64>>>(ntiles, N);
    gemm_tc<<<gemm_grid, 256>>>(x, W_gat, p_h, N);
    k_scanC<<<ntiles, 256>>>(N);
    k_fill<<<(E + 255) / 256, 256>>>(ei, E);
    k_attn<<<(N * 4 + 255) / 256, 256>>>(att_src, att_dst, N);

    // GAT aggregation (out1 pre-scaled by dinv)
    k_gat_agg<<<(N * 32 + 255) / 256, 256>>>(b_gat, bn1_w, bn1_b, N);

    // GCN
    gemm_tc<<<gemm_grid, 256>>>(p_out1, W_gcn, p_h2, N);
    k_gcn_agg<<<(N * 32 + 255) / 256, 256>>>(b_gcn, bn2_w, bn2_b, W_gate, b_gate, N);

    // Pooling + FC (+ deg re-zero)
    k_pool_final<<<GSEG, 256>>>(batch, W_fc, b_fc, out, N);
}

// round 8
// speedup vs baseline: 1.4459x; 1.4459x over previous
#include <cuda_runtime.h>
#include <cuda_fp16.h>
#include <mma.h>
#include <math.h>

using namespace nvcuda;

#define NMAX 50000
#define NPAD 50048   // NMAX rounded up to 128 (unguarded wmma tile stores)
#define EMAX 800000
#define GSEG 64
#define STILE 1024

// ---------------- scratch (device globals; zero-initialized at module load) ----------------
__device__ float g_h[NPAD * 128];      // GAT-transformed features (padded)
__device__ float g_asrc[NMAX * 4];
__device__ float g_adst[NMAX * 4];
__device__ float g_out1[NMAX * 128];   // GAT output, pre-scaled by dinv[node]
__device__ float g_h2[NPAD * 128];     // out1 @ W_gcn (padded)
__device__ float g_out2[NMAX * 128];
__device__ float g_dinv[NMAX];
__device__ float g_eg[NMAX];
__device__ int   g_deg[NMAX];
__device__ int   g_rowptr[NMAX + 1];
__device__ int   g_wpos[NMAX];
__device__ int   g_col[EMAX + NMAX];
__device__ int   g_tsum[64];
__device__ int   g_toff[64];

__device__ __forceinline__ float lrelu(float v) { return fmaxf(v, 0.2f * v); }
__device__ __forceinline__ float elu(float v) { return v > 0.f ? v : __expf(v) - 1.f; }

// ---------------- CSR build ----------------
__global__ void k_count(const int* __restrict__ ei, int E) {
    int i = blockIdx.x * blockDim.x + threadIdx.x;
    if (i < E) atomicAdd(&g_deg[__ldg(ei + E + i)], 1);
}

__global__ void k_scanA(int N) {
    __shared__ int red[8];
    int t = threadIdx.x;
    int i0 = blockIdx.x * STILE + t * 4;
    int s = 0;
#pragma unroll
    for (int j = 0; j < 4; j++) {
        int i = i0 + j;
        if (i < N) s += g_deg[i] + 1;
    }
#pragma unroll
    for (int o = 16; o; o >>= 1) s += __shfl_down_sync(0xffffffffu, s, o);
    if ((t & 31) == 0) red[t >> 5] = s;
    __syncthreads();
    if (t == 0) {
        int tot = 0;
#pragma unroll
        for (int i = 0; i < 8; i++) tot += red[i];
        g_tsum[blockIdx.x] = tot;
    }
}

__global__ void k_scanB(int ntiles, int N) {
    __shared__ int w0sum;
    int t = threadIdx.x;
    int own = (t < ntiles) ? g_tsum[t] : 0;
    int v = own;
#pragma unroll
    for (int o = 1; o < 32; o <<= 1) {
        int u = __shfl_up_sync(0xffffffffu, v, o);
        if ((t & 31) >= o) v += u;
    }
    if (t == 31) w0sum = v;
    __syncthreads();
    if (t >= 32) v += w0sum;
    if (t < ntiles) g_toff[t] = v - own;
    if (t == ntiles - 1) g_rowptr[N] = v;
}

__global__ void k_scanC(int N) {
    __shared__ int sm[256];
    int t = threadIdx.x;
    int i0 = blockIdx.x * STILE + t * 4;
    int v[4], ts = 0;
#pragma unroll
    for (int j = 0; j < 4; j++) {
        int i = i0 + j;
        v[j] = (i < N) ? g_deg[i] + 1 : 0;
        ts += v[j];
    }
    sm[t] = ts;
    __syncthreads();
    for (int o = 1; o < 256; o <<= 1) {
        int x = (t >= o) ? sm[t - o] : 0;
        __syncthreads();
        sm[t] += x;
        __syncthreads();
    }
    int base = g_toff[blockIdx.x] + sm[t] - ts;
#pragma unroll
    for (int j = 0; j < 4; j++) {
        int i = i0 + j;
        if (i < N) {
            g_rowptr[i] = base;
            g_col[base] = i;
            g_wpos[i] = base + 1;
            g_dinv[i] = rsqrtf((float)v[j]);
            base += v[j];
        }
    }
}

__global__ void k_fill(const int* __restrict__ ei, int E) {
    int i = blockIdx.x * blockDim.x + threadIdx.x;
    if (i >= E) return;
    int s = __ldg(ei + i);
    int d = __ldg(ei + E + i);
    int pos = atomicAdd(&g_wpos[d], 1);
    g_col[pos] = s;
}

// ---------------- fp16 hi/lo split tensor GEMM: C[NPAD,128] = A[N,128] @ B[128,128] ----
// x = hi + lo (fp16 pair, ~2^-24 rel).  C = Ah*Bh + Al*Bh + Ah*Bl  (missing AlBl ~2^-24).
// Block: 128x128 tile, 8 warps (2 row groups x 4 col groups), warp tile 64x32.
// SMEM per 32-k chunk: sA = [Ah(32) | Al(32)] halves, sB = [Bh(32) ; Bl(32)] rows.
#define SA_PITCH 80   // halves; 160B = 32B-aligned rows
#define SB_PITCH 144  // halves; 288B = 32B-aligned rows
__global__ __launch_bounds__(256, 2) void gemm_f16(
    const float* __restrict__ A, const float* __restrict__ B,
    float* __restrict__ C, int nrows) {
    __shared__ __half sA[128][SA_PITCH];
    __shared__ __half sB[64][SB_PITCH];

    int tid = threadIdx.x;
    int wid = tid >> 5;
    int warp_m = wid & 1;    // 0..1
    int warp_n = wid >> 1;   // 0..3
    int row0 = blockIdx.x * 128;

    wmma::fragment<wmma::accumulator, 16, 16, 16, float> acc[4][2];
#pragma unroll
    for (int mt = 0; mt < 4; mt++)
#pragma unroll
        for (int nt = 0; nt < 2; nt++) wmma::fill_fragment(acc[mt][nt], 0.f);

    // 6 fragment-offset pairs implementing the 3 split products
    const int KA[6] = {0, 16, 32, 48, 0, 16};   // sA col offset (halves)
    const int KB[6] = {0, 16, 0, 16, 32, 48};   // sB row offset

    for (int k0 = 0; k0 < 128; k0 += 32) {
        __syncthreads();
        // A chunk: 128 rows x 32 fp32 -> hi at sA[r][g*4], lo at sA[r][32+g*4]
#pragma unroll
        for (int u = 0; u < 4; u++) {
            int it = tid + u * 256;
            int r = it >> 3, g = it & 7;
            float4 v = make_float4(0.f, 0.f, 0.f, 0.f);
            if (row0 + r < nrows)
                v = *(const float4*)(A + (long long)(row0 + r) * 128 + k0 + g * 4);
            __half hh[4], hl[4];
            hh[0] = __float2half_rn(v.x); hl[0] = __float2half_rn(v.x - __half2float(hh[0]));
            hh[1] = __float2half_rn(v.y); hl[1] = __float2half_rn(v.y - __half2float(hh[1]));
            hh[2] = __float2half_rn(v.z); hl[2] = __float2half_rn(v.z - __half2float(hh[2]));
            hh[3] = __float2half_rn(v.w); hl[3] = __float2half_rn(v.w - __half2float(hh[3]));
            *(uint2*)&sA[r][g * 4]      = *(uint2*)hh;
            *(uint2*)&sA[r][32 + g * 4] = *(uint2*)hl;
        }
        // B chunk: 32 rows x 128 fp32 -> hi at sB[kr][c], lo at sB[32+kr][c]
#pragma unroll
        for (int u = 0; u < 4; u++) {
            int it = tid + u * 256;
            int kr = it >> 5, c = (it & 31) * 4;
            float4 v = *(const float4*)(B + (long long)(k0 + kr) * 128 + c);
            __half hh[4], hl[4];
            hh[0] = __float2half_rn(v.x); hl[0] = __float2half_rn(v.x - __half2float(hh[0]));
            hh[1] = __float2half_rn(v.y); hl[1] = __float2half_rn(v.y - __half2float(hh[1]));
            hh[2] = __float2half_rn(v.z); hl[2] = __float2half_rn(v.z - __half2float(hh[2]));
            hh[3] = __float2half_rn(v.w); hl[3] = __float2half_rn(v.w - __half2float(hh[3]));
            *(uint2*)&sB[kr][c]      = *(uint2*)hh;
            *(uint2*)&sB[32 + kr][c] = *(uint2*)hl;
        }
        __syncthreads();

#pragma unroll
        for (int p = 0; p < 6; p++) {
            wmma::fragment<wmma::matrix_b, 16, 16, 16, __half, wmma::row_major> bf[2];
#pragma unroll
            for (int nt = 0; nt < 2; nt++)
                wmma::load_matrix_sync(bf[nt], &sB[KB[p]][warp_n * 32 + nt * 16], SB_PITCH);
#pragma unroll
            for (int mt = 0; mt < 4; mt++) {
                wmma::fragment<wmma::matrix_a, 16, 16, 16, __half, wmma::row_major> af;
                wmma::load_matrix_sync(af, &sA[warp_m * 64 + mt * 16][KA[p]], SA_PITCH);
#pragma unroll
                for (int nt = 0; nt < 2; nt++)
                    wmma::mma_sync(acc[mt][nt], af, bf[nt], acc[mt][nt]);
            }
        }
    }

    // store (C padded to NPAD rows, unguarded)
#pragma unroll
    for (int mt = 0; mt < 4; mt++)
#pragma unroll
        for (int nt = 0; nt < 2; nt++) {
            int r = row0 + warp_m * 64 + mt * 16;
            int c = warp_n * 32 + nt * 16;
            wmma::store_matrix_sync(C + (long long)r * 128 + c, acc[mt][nt],
                                    128, wmma::mem_row_major);
        }
}

// ---------------- attention logits per node/head ----------------
__global__ void k_attn(const float* __restrict__ att_src,
                       const float* __restrict__ att_dst, int N) {
    int t = blockIdx.x * blockDim.x + threadIdx.x;
    if (t >= N * 4) return;
    int n = t >> 2, hd = t & 3;
    const float* hp = g_h + (long long)n * 128 + hd * 32;
    float s1 = 0.f, s2 = 0.f;
#pragma unroll
    for (int c = 0; c < 32; c += 4) {
        float4 hv = *(const float4*)(hp + c);
        float4 as = *(const float4*)(att_src + hd * 32 + c);
        float4 ad = *(const float4*)(att_dst + hd * 32 + c);
        s1 += hv.x * as.x + hv.y * as.y + hv.z * as.z + hv.w * as.w;
        s2 += hv.x * ad.x + hv.y * ad.y + hv.z * ad.z + hv.w * ad.w;
    }
    g_asrc[t] = s1;
    g_adst[t] = s2;
}

// ---------------- GAT aggregation: warp per dst node; out1 pre-scaled by dinv ----------------
__global__ void k_gat_agg(const float* __restrict__ b_gat,
                          const float* __restrict__ bn_w,
                          const float* __restrict__ bn_b, int N) {
    int t = blockIdx.x * blockDim.x + threadIdx.x;
    int node = t >> 5, lane = t & 31;
    if (node >= N) return;
    int head = lane >> 3;
    int beg = g_rowptr[node], end = g_rowptr[node + 1];
    float adh = g_adst[node * 4 + head];

    float4 acc = make_float4(0.f, 0.f, 0.f, 0.f);
    float den = 0.f;
    int i = beg;
    for (; i + 4 <= end; i += 4) {
        int s0 = __ldg(&g_col[i + 0]);
        int s1 = __ldg(&g_col[i + 1]);
        int s2 = __ldg(&g_col[i + 2]);
        int s3 = __ldg(&g_col[i + 3]);
        float a0 = __ldg(&g_asrc[s0 * 4 + head]);
        float a1 = __ldg(&g_asrc[s1 * 4 + head]);
        float a2 = __ldg(&g_asrc[s2 * 4 + head]);
        float a3 = __ldg(&g_asrc[s3 * 4 + head]);
        float4 h0 = *(const float4*)(g_h + (long long)s0 * 128 + lane * 4);
        float4 h1 = *(const float4*)(g_h + (long long)s1 * 128 + lane * 4);
        float4 h2 = *(const float4*)(g_h + (long long)s2 * 128 + lane * 4);
        float4 h3 = *(const float4*)(g_h + (long long)s3 * 128 + lane * 4);
        float e0 = __expf(lrelu(a0 + adh));
        float e1 = __expf(lrelu(a1 + adh));
        float e2 = __expf(lrelu(a2 + adh));
        float e3 = __expf(lrelu(a3 + adh));
        den += (e0 + e1) + (e2 + e3);
        acc.x += e0 * h0.x + e1 * h1.x + e2 * h2.x + e3 * h3.x;
        acc.y += e0 * h0.y + e1 * h1.y + e2 * h2.y + e3 * h3.y;
        acc.z += e0 * h0.z + e1 * h1.z + e2 * h2.z + e3 * h3.z;
        acc.w += e0 * h0.w + e1 * h1.w + e2 * h2.w + e3 * h3.w;
    }
    for (; i < end; i++) {
        int s = __ldg(&g_col[i]);
        float a = __ldg(&g_asrc[s * 4 + head]);
        float e = __expf(lrelu(a + adh));
        den += e;
        float4 hv = *(const float4*)(g_h + (long long)s * 128 + lane * 4);
        acc.x += e * hv.x; acc.y += e * hv.y;
        acc.z += e * hv.z; acc.w += e * hv.w;
    }
    float inv = 1.f / (den + 1e-16f);
    float dd = g_dinv[node];   // GCN src-side normalization folded in
    int c4 = lane * 4;
    float4 bg = *(const float4*)(b_gat + c4);
    float4 wv = *(const float4*)(bn_w + c4);
    float4 bv = *(const float4*)(bn_b + c4);
    acc.x = (elu(acc.x * inv + bg.x) * wv.x + bv.x) * dd;
    acc.y = (elu(acc.y * inv + bg.y) * wv.y + bv.y) * dd;
    acc.z = (elu(acc.z * inv + bg.z) * wv.z + bv.z) * dd;
    acc.w = (elu(acc.w * inv + bg.w) * wv.w + bv.w) * dd;
    *(float4*)(g_out1 + (long long)node * 128 + c4) = acc;
}

// ---------------- GCN aggregation + post + gate (dinv[src] pre-folded into out1) ----------------
__global__ void k_gcn_agg(const float* __restrict__ b_gcn,
                          const float* __restrict__ bn_w,
                          const float* __restrict__ bn_b,
                          const float* __restrict__ W_gate,
                          const float* __restrict__ b_gate, int N) {
    int t = blockIdx.x * blockDim.x + threadIdx.x;
    int node = t >> 5, lane = t & 31;
    if (node >= N) return;
    int beg = g_rowptr[node], end = g_rowptr[node + 1];

    float4 acc = make_float4(0.f, 0.f, 0.f, 0.f);
    int i = beg;
    for (; i + 4 <= end; i += 4) {
        int s0 = __ldg(&g_col[i + 0]);
        int s1 = __ldg(&g_col[i + 1]);
        int s2 = __ldg(&g_col[i + 2]);
        int s3 = __ldg(&g_col[i + 3]);
        float4 h0 = *(const float4*)(g_h2 + (long long)s0 * 128 + lane * 4);
        float4 h1 = *(const float4*)(g_h2 + (long long)s1 * 128 + lane * 4);
        float4 h2 = *(const float4*)(g_h2 + (long long)s2 * 128 + lane * 4);
        float4 h3 = *(const float4*)(g_h2 + (long long)s3 * 128 + lane * 4);
        acc.x += (h0.x + h1.x) + (h2.x + h3.x);
        acc.y += (h0.y + h1.y) + (h2.y + h3.y);
        acc.z += (h0.z + h1.z) + (h2.z + h3.z);
        acc.w += (h0.w + h1.w) + (h2.w + h3.w);
    }
    for (; i < end; i++) {
        int s = __ldg(&g_col[i]);
        float4 hv = *(const float4*)(g_h2 + (long long)s * 128 + lane * 4);
        acc.x += hv.x; acc.y += hv.y; acc.z += hv.z; acc.w += hv.w;
    }
    float dd = g_dinv[node];
    int c4 = lane * 4;
    float4 bg = *(const float4*)(b_gcn + c4);
    float4 wv = *(const float4*)(bn_w + c4);
    float4 bv = *(const float4*)(bn_b + c4);
    acc.x = elu(acc.x * dd + bg.x) * wv.x + bv.x;
    acc.y = elu(acc.y * dd + bg.y) * wv.y + bv.y;
    acc.z = elu(acc.z * dd + bg.z) * wv.z + bv.z;
    acc.w = elu(acc.w * dd + bg.w) * wv.w + bv.w;
    *(float4*)(g_out2 + (long long)node * 128 + c4) = acc;

    float4 wg = *(const float4*)(W_gate + c4);
    float p = acc.x * wg.x + acc.y * wg.y + acc.z * wg.z + acc.w * wg.w;
#pragma unroll
    for (int o = 16; o; o >>= 1) p += __shfl_xor_sync(0xffffffffu, p, o);
    if (lane == 0) g_eg[node] = __expf(p + b_gate[0]);
}

__device__ __forceinline__ int lower_bound(const int* __restrict__ batch, int N, int key) {
    int lo = 0, hi = N;
    while (lo < hi) {
        int mid = (lo + hi) >> 1;
        if (__ldg(batch + mid) < key) lo = mid + 1; else hi = mid;
    }
    return lo;
}

// ---------------- pooling + final FC fused; tail re-zeroes g_deg ----------------
__global__ void k_pool_final(const int* __restrict__ batch,
                             const float* __restrict__ W_fc,
                             const float* __restrict__ b_fc,
                             float* __restrict__ out, int N) {
    __shared__ float red[8];
    __shared__ float s_acc[256];
    __shared__ float s_inv;
    int gph = blockIdx.x;
    int t = threadIdx.x;
    int lane = t & 31, wrp = t >> 5;
    int beg = lower_bound(batch, N, gph);
    int end = lower_bound(batch, N, gph + 1);

    float s = 0.f;
    for (int n = beg + t; n < end; n += 256) s += g_eg[n];
#pragma unroll
    for (int o = 16; o; o >>= 1) s += __shfl_xor_sync(0xffffffffu, s, o);
    if (lane == 0) red[wrp] = s;
    __syncthreads();
    if (t == 0) {
        float tot = 0.f;
#pragma unroll
        for (int i = 0; i < 8; i++) tot += red[i];
        s_inv = 1.f / (tot + 1e-16f);
    }
    __syncthreads();
    float inv = s_inv;

    int half = t >> 7, c = t & 127;
    float acc = 0.f;
    int n = beg + half;
    for (; n + 8 <= end; n += 8) {
        acc += g_eg[n + 0] * g_out2[(long long)(n + 0) * 128 + c];
        acc += g_eg[n + 2] * g_out2[(long long)(n + 2) * 128 + c];
        acc += g_eg[n + 4] * g_out2[(long long)(n + 4) * 128 + c];
        acc += g_eg[n + 6] * g_out2[(long long)(n + 6) * 128 + c];
    }
    for (; n < end; n += 2)
        acc += g_eg[n] * g_out2[(long long)n * 128 + c];
    s_acc[t] = acc;
    __syncthreads();

    if (t < 128) {
        float p = (s_acc[t] + s_acc[t + 128]) * inv * W_fc[t];
#pragma unroll
        for (int o = 16; o; o >>= 1) p += __shfl_xor_sync(0xffffffffu, p, o);
        if (lane == 0) red[wrp] = p;
    }
    __syncthreads();
    if (t == 0) out[gph] = red[0] + red[1] + red[2] + red[3] + b_fc[0];

    int gid = gph * 256 + t;
    for (int k = gid; k < NMAX; k += GSEG * 256) g_deg[k] = 0;
}

extern "C" void kernel_launch(void* const* d_in, const int* in_sizes, int n_in,
                              void* d_out, int out_size) {
    const float* x       = (const float*)d_in[0];
    const int*   ei      = (const int*)d_in[1];
    const int*   batch   = (const int*)d_in[2];
    const float* W_gat   = (const float*)d_in[3];
    const float* att_src = (const float*)d_in[4];
    const float* att_dst = (const float*)d_in[5];
    const float* b_gat   = (const float*)d_in[6];
    const float* bn1_w   = (const float*)d_in[7];
    const float* bn1_b   = (const float*)d_in[8];
    const float* W_gcn   = (const float*)d_in[9];
    const float* b_gcn   = (const float*)d_in[10];
    const float* bn2_w   = (const float*)d_in[11];
    const float* bn2_b   = (const float*)d_in[12];
    const float* W_gate  = (const float*)d_in[13];
    const float* b_gate  = (const float*)d_in[14];
    const float* W_fc    = (const float*)d_in[15];
    const float* b_fc    = (const float*)d_in[16];
    float* out = (float*)d_out;

    int N = in_sizes[0] / 128;
    int E = in_sizes[1] / 2;
    if (N > NMAX) N = NMAX;
    if (E > EMAX) E = EMAX;
    int ntiles = (N + STILE - 1) / STILE;

    float *p_h, *p_out1, *p_h2;
    cudaGetSymbolAddress((void**)&p_h, g_h);
    cudaGetSymbolAddress((void**)&p_out1, g_out1);
    cudaGetSymbolAddress((void**)&p_h2, g_h2);

    int gemm_grid = (N + 127) / 128;

    // CSR build — gemm1 is launch #4 (ncu capture slot)
    k_count<<<(E + 255) / 256, 256>>>(ei, E);
    k_scanA<<<ntiles, 256>>>(N);
    k_scanB<<<1, 64>>>(ntiles, N);
    gemm_f16<<<gemm_grid, 256>>>(x, W_gat, p_h, N);
    k_scanC<<<ntiles, 256>>>(N);
    k_fill<<<(E + 255) / 256, 256>>>(ei, E);
    k_attn<<<(N * 4 + 255) / 256, 256>>>(att_src, att_dst, N);

    // GAT aggregation (out1 pre-scaled by dinv)
    k_gat_agg<<<(N * 32 + 255) / 256, 256>>>(b_gat, bn1_w, bn1_b, N);

    // GCN
    gemm_f16<<<gemm_grid, 256>>>(p_out1, W_gcn, p_h2, N);
    k_gcn_agg<<<(N * 32 + 255) / 256, 256>>>(b_gcn, bn2_w, bn2_b, W_gate, b_gate, N);

    // Pooling + FC (+ deg re-zero)
    k_pool_final<<<GSEG, 256>>>(batch, W_fc, b_fc, out, N);
}

// round 11
// speedup vs baseline: 1.5808x; 1.0933x over previous
#include <cuda_runtime.h>
#include <cuda_fp16.h>
#include <mma.h>
#include <math.h>

using namespace nvcuda;

#define NMAX 50000
#define NPAD 50048   // NMAX rounded up to 128 (unguarded wmma tile stores)
#define EMAX 800000
#define GSEG 64
#define STILE 1024

// ---------------- scratch (device globals; zero-initialized at module load) ----------------
__device__ __half g_hh[NPAD * 128];    // GAT-transformed features, fp16
__device__ __half g_h2h[NPAD * 128];   // out1 @ W_gcn, fp16
__device__ float g_asrc[NMAX * 4];
__device__ float g_adst[NMAX * 4];
__device__ float g_out1[NMAX * 128];   // GAT output, pre-scaled by dinv[node] (fp32)
__device__ float g_out2[NMAX * 128];
__device__ float g_dinv[NMAX];
__device__ float g_eg[NMAX];
__device__ int   g_deg[NMAX];
__device__ int   g_rowptr[NMAX + 1];
__device__ int   g_wpos[NMAX];
__device__ int   g_col[EMAX + NMAX];
__device__ int   g_tsum[64];
__device__ int   g_toff[64];

__device__ __forceinline__ float lrelu(float v) { return fmaxf(v, 0.2f * v); }
__device__ __forceinline__ float elu(float v) { return v > 0.f ? v : __expf(v) - 1.f; }

// load 4 consecutive halves -> float4
__device__ __forceinline__ float4 ldh4(const __half* p) {
    uint2 u = *(const uint2*)p;
    __half2 a = *(__half2*)&u.x;
    __half2 b = *(__half2*)&u.y;
    float2 fa = __half22float2(a);
    float2 fb = __half22float2(b);
    return make_float4(fa.x, fa.y, fb.x, fb.y);
}

// ---------------- CSR build ----------------
__global__ void k_count(const int* __restrict__ ei, int E) {
    int i = blockIdx.x * blockDim.x + threadIdx.x;
    if (i < E) atomicAdd(&g_deg[__ldg(ei + E + i)], 1);
}

__global__ void k_scanA(int N) {
    __shared__ int red[8];
    int t = threadIdx.x;
    int i0 = blockIdx.x * STILE + t * 4;
    int s = 0;
#pragma unroll
    for (int j = 0; j < 4; j++) {
        int i = i0 + j;
        if (i < N) s += g_deg[i] + 1;
    }
#pragma unroll
    for (int o = 16; o; o >>= 1) s += __shfl_down_sync(0xffffffffu, s, o);
    if ((t & 31) == 0) red[t >> 5] = s;
    __syncthreads();
    if (t == 0) {
        int tot = 0;
#pragma unroll
        for (int i = 0; i < 8; i++) tot += red[i];
        g_tsum[blockIdx.x] = tot;
    }
}

__global__ void k_scanB(int ntiles, int N) {
    __shared__ int w0sum;
    int t = threadIdx.x;
    int own = (t < ntiles) ? g_tsum[t] : 0;
    int v = own;
#pragma unroll
    for (int o = 1; o < 32; o <<= 1) {
        int u = __shfl_up_sync(0xffffffffu, v, o);
        if ((t & 31) >= o) v += u;
    }
    if (t == 31) w0sum = v;
    __syncthreads();
    if (t >= 32) v += w0sum;
    if (t < ntiles) g_toff[t] = v - own;
    if (t == ntiles - 1) g_rowptr[N] = v;
}

__global__ void k_scanC(int N) {
    __shared__ int sm[256];
    int t = threadIdx.x;
    int i0 = blockIdx.x * STILE + t * 4;
    int v[4], ts = 0;
#pragma unroll
    for (int j = 0; j < 4; j++) {
        int i = i0 + j;
        v[j] = (i < N) ? g_deg[i] + 1 : 0;
        ts += v[j];
    }
    sm[t] = ts;
    __syncthreads();
    for (int o = 1; o < 256; o <<= 1) {
        int x = (t >= o) ? sm[t - o] : 0;
        __syncthreads();
        sm[t] += x;
        __syncthreads();
    }
    int base = g_toff[blockIdx.x] + sm[t] - ts;
#pragma unroll
    for (int j = 0; j < 4; j++) {
        int i = i0 + j;
        if (i < N) {
            g_rowptr[i] = base;
            g_col[base] = i;
            g_wpos[i] = base + 1;
            g_dinv[i] = rsqrtf((float)v[j]);
            base += v[j];
        }
    }
}

__global__ void k_fill(const int* __restrict__ ei, int E) {
    int i = blockIdx.x * blockDim.x + threadIdx.x;
    if (i >= E) return;
    int s = __ldg(ei + i);
    int d = __ldg(ei + E + i);
    int pos = atomicAdd(&g_wpos[d], 1);
    g_col[pos] = s;
}

// ---------------- fp16 hi/lo split tensor GEMM: C[NPAD,128](fp16) = A[N,128] @ B[128,128] ----
// C = Ah*Bh + Al*Bh + Ah*Bl (fp32 accum, ~2^-24 missing term).
// MODE 0: epilogue also computes attention logits from the EXACT fp32 accumulators.
//         Each warp's 32-col group == one head (head = warp_n).
// MODE 1: plain fp16 store.
#define SA_PITCH 80   // halves
#define SB_PITCH 144  // halves
template <int MODE>
__global__ __launch_bounds__(256, 2) void gemm_f16(
    const float* __restrict__ A, const float* __restrict__ B,
    __half* __restrict__ C, int nrows,
    const float* __restrict__ att_src, const float* __restrict__ att_dst) {
    __shared__ __align__(16) __half sA[128][SA_PITCH];
    __shared__ __align__(16) __half sB[64][SB_PITCH];

    int tid = threadIdx.x;
    int wid = tid >> 5;
    int lane = tid & 31;
    int warp_m = wid & 1;    // 0..1
    int warp_n = wid >> 1;   // 0..3  (== head for MODE 0)
    int row0 = blockIdx.x * 128;

    wmma::fragment<wmma::accumulator, 16, 16, 16, float> acc[4][2];
#pragma unroll
    for (int mt = 0; mt < 4; mt++)
#pragma unroll
        for (int nt = 0; nt < 2; nt++) wmma::fill_fragment(acc[mt][nt], 0.f);

    const int KA[6] = {0, 16, 32, 48, 0, 16};
    const int KB[6] = {0, 16, 0, 16, 32, 48};

    for (int k0 = 0; k0 < 128; k0 += 32) {
        __syncthreads();
#pragma unroll
        for (int u = 0; u < 4; u++) {
            int it = tid + u * 256;
            int r = it >> 3, g = it & 7;
            float4 v = make_float4(0.f, 0.f, 0.f, 0.f);
            if (row0 + r < nrows)
                v = *(const float4*)(A + (long long)(row0 + r) * 128 + k0 + g * 4);
            __half hh[4], hl[4];
            hh[0] = __float2half_rn(v.x); hl[0] = __float2half_rn(v.x - __half2float(hh[0]));
            hh[1] = __float2half_rn(v.y); hl[1] = __float2half_rn(v.y - __half2float(hh[1]));
            hh[2] = __float2half_rn(v.z); hl[2] = __float2half_rn(v.z - __half2float(hh[2]));
            hh[3] = __float2half_rn(v.w); hl[3] = __float2half_rn(v.w - __half2float(hh[3]));
            *(uint2*)&sA[r][g * 4]      = *(uint2*)hh;
            *(uint2*)&sA[r][32 + g * 4] = *(uint2*)hl;
        }
#pragma unroll
        for (int u = 0; u < 4; u++) {
            int it = tid + u * 256;
            int kr = it >> 5, c = (it & 31) * 4;
            float4 v = *(const float4*)(B + (long long)(k0 + kr) * 128 + c);
            __half hh[4], hl[4];
            hh[0] = __float2half_rn(v.x); hl[0] = __float2half_rn(v.x - __half2float(hh[0]));
            hh[1] = __float2half_rn(v.y); hl[1] = __float2half_rn(v.y - __half2float(hh[1]));
            hh[2] = __float2half_rn(v.z); hl[2] = __float2half_rn(v.z - __half2float(hh[2]));
            hh[3] = __float2half_rn(v.w); hl[3] = __float2half_rn(v.w - __half2float(hh[3]));
            *(uint2*)&sB[kr][c]      = *(uint2*)hh;
            *(uint2*)&sB[32 + kr][c] = *(uint2*)hl;
        }
        __syncthreads();

#pragma unroll
        for (int p = 0; p < 6; p++) {
            wmma::fragment<wmma::matrix_b, 16, 16, 16, __half, wmma::row_major> bf[2];
#pragma unroll
            for (int nt = 0; nt < 2; nt++)
                wmma::load_matrix_sync(bf[nt], &sB[KB[p]][warp_n * 32 + nt * 16], SB_PITCH);
#pragma unroll
            for (int mt = 0; mt < 4; mt++) {
                wmma::fragment<wmma::matrix_a, 16, 16, 16, __half, wmma::row_major> af;
                wmma::load_matrix_sync(af, &sA[warp_m * 64 + mt * 16][KA[p]], SA_PITCH);
#pragma unroll
                for (int nt = 0; nt < 2; nt++)
                    wmma::mma_sync(acc[mt][nt], af, bf[nt], acc[mt][nt]);
            }
        }
    }

    // ---------------- epilogue: stage fp32 accum -> fp16 C (+ logits for MODE 0) ----------
    __syncthreads();  // done with sA as mma operand; reuse as fp32 staging
    float* stg = ((float*)&sA[0][0]) + wid * 576;  // 16x36 fp32 per warp (2304 B)
    int lrow = lane & 15;
    int lch = (lane >> 4) * 16;   // col half within the 32-col head group

#pragma unroll
    for (int mt = 0; mt < 4; mt++) {
        wmma::store_matrix_sync(stg, acc[mt][0], 36, wmma::mem_row_major);
        wmma::store_matrix_sync(stg + 16, acc[mt][1], 36, wmma::mem_row_major);
        __syncwarp();
        int r = row0 + warp_m * 64 + mt * 16 + lrow;
        float v[16];
#pragma unroll
        for (int j = 0; j < 16; j++) v[j] = stg[lrow * 36 + lch + j];
        __half hv[16];
#pragma unroll
        for (int j = 0; j < 16; j++) hv[j] = __float2half_rn(v[j]);
        // 16 halves = 32 bytes = TWO uint4 stores (R9 bug: only one was issued)
        uint4* cp = (uint4*)(C + (long long)r * 128 + warp_n * 32 + lch);
        cp[0] = ((uint4*)hv)[0];
        cp[1] = ((uint4*)hv)[1];
        if (MODE == 0) {
            float ps = 0.f, pd = 0.f;
#pragma unroll
            for (int j = 0; j < 16; j++) {
                ps += v[j] * __ldg(att_src + warp_n * 32 + lch + j);
                pd += v[j] * __ldg(att_dst + warp_n * 32 + lch + j);
            }
            ps += __shfl_down_sync(0xffffffffu, ps, 16);
            pd += __shfl_down_sync(0xffffffffu, pd, 16);
            if (lane < 16 && r < nrows) {
                g_asrc[r * 4 + warp_n] = ps;
                g_adst[r * 4 + warp_n] = pd;
            }
        }
        __syncwarp();
    }
}

// ---------------- GAT aggregation: warp per dst node; exact alpha, fp16 messages ----------------
__global__ void k_gat_agg(const float* __restrict__ b_gat,
                          const float* __restrict__ bn_w,
                          const float* __restrict__ bn_b, int N) {
    int t = blockIdx.x * blockDim.x + threadIdx.x;
    int node = t >> 5, lane = t & 31;
    if (node >= N) return;
    int head = lane >> 3;
    int beg = g_rowptr[node], end = g_rowptr[node + 1];
    float adh = g_adst[node * 4 + head];

    float4 acc = make_float4(0.f, 0.f, 0.f, 0.f);
    float den = 0.f;
    int i = beg;
    for (; i + 4 <= end; i += 4) {
        int s0 = __ldg(&g_col[i + 0]);
        int s1 = __ldg(&g_col[i + 1]);
        int s2 = __ldg(&g_col[i + 2]);
        int s3 = __ldg(&g_col[i + 3]);
        float a0 = __ldg(&g_asrc[s0 * 4 + head]);
        float a1 = __ldg(&g_asrc[s1 * 4 + head]);
        float a2 = __ldg(&g_asrc[s2 * 4 + head]);
        float a3 = __ldg(&g_asrc[s3 * 4 + head]);
        float4 h0 = ldh4(g_hh + (long long)s0 * 128 + lane * 4);
        float4 h1 = ldh4(g_hh + (long long)s1 * 128 + lane * 4);
        float4 h2 = ldh4(g_hh + (long long)s2 * 128 + lane * 4);
        float4 h3 = ldh4(g_hh + (long long)s3 * 128 + lane * 4);
        float e0 = __expf(lrelu(a0 + adh));
        float e1 = __expf(lrelu(a1 + adh));
        float e2 = __expf(lrelu(a2 + adh));
        float e3 = __expf(lrelu(a3 + adh));
        den += (e0 + e1) + (e2 + e3);
        acc.x += e0 * h0.x + e1 * h1.x + e2 * h2.x + e3 * h3.x;
        acc.y += e0 * h0.y + e1 * h1.y + e2 * h2.y + e3 * h3.y;
        acc.z += e0 * h0.z + e1 * h1.z + e2 * h2.z + e3 * h3.z;
        acc.w += e0 * h0.w + e1 * h1.w + e2 * h2.w + e3 * h3.w;
    }
    for (; i < end; i++) {
        int s = __ldg(&g_col[i]);
        float a = __ldg(&g_asrc[s * 4 + head]);
        float e = __expf(lrelu(a + adh));
        den += e;
        float4 hv = ldh4(g_hh + (long long)s * 128 + lane * 4);
        acc.x += e * hv.x; acc.y += e * hv.y;
        acc.z += e * hv.z; acc.w += e * hv.w;
    }
    float inv = 1.f / (den + 1e-16f);
    float dd = g_dinv[node];   // GCN src-side normalization folded in
    int c4 = lane * 4;
    float4 bg = *(const float4*)(b_gat + c4);
    float4 wv = *(const float4*)(bn_w + c4);
    float4 bv = *(const float4*)(bn_b + c4);
    acc.x = (elu(acc.x * inv + bg.x) * wv.x + bv.x) * dd;
    acc.y = (elu(acc.y * inv + bg.y) * wv.y + bv.y) * dd;
    acc.z = (elu(acc.z * inv + bg.z) * wv.z + bv.z) * dd;
    acc.w = (elu(acc.w * inv + bg.w) * wv.w + bv.w) * dd;
    *(float4*)(g_out1 + (long long)node * 128 + c4) = acc;
}

// ---------------- GCN aggregation + post + gate (fp16 h2, dinv[src] pre-folded) ----------------
__global__ void k_gcn_agg(const float* __restrict__ b_gcn,
                          const float* __restrict__ bn_w,
                          const float* __restrict__ bn_b,
                          const float* __restrict__ W_gate,
                          const float* __restrict__ b_gate, int N) {
    int t = blockIdx.x * blockDim.x + threadIdx.x;
    int node = t >> 5, lane = t & 31;
    if (node >= N) return;
    int beg = g_rowptr[node], end = g_rowptr[node + 1];

    float4 acc = make_float4(0.f, 0.f, 0.f, 0.f);
    int i = beg;
    for (; i + 4 <= end; i += 4) {
        int s0 = __ldg(&g_col[i + 0]);
        int s1 = __ldg(&g_col[i + 1]);
        int s2 = __ldg(&g_col[i + 2]);
        int s3 = __ldg(&g_col[i + 3]);
        float4 h0 = ldh4(g_h2h + (long long)s0 * 128 + lane * 4);
        float4 h1 = ldh4(g_h2h + (long long)s1 * 128 + lane * 4);
        float4 h2 = ldh4(g_h2h + (long long)s2 * 128 + lane * 4);
        float4 h3 = ldh4(g_h2h + (long long)s3 * 128 + lane * 4);
        acc.x += (h0.x + h1.x) + (h2.x + h3.x);
        acc.y += (h0.y + h1.y) + (h2.y + h3.y);
        acc.z += (h0.z + h1.z) + (h2.z + h3.z);
        acc.w += (h0.w + h1.w) + (h2.w + h3.w);
    }
    for (; i < end; i++) {
        int s = __ldg(&g_col[i]);
        float4 hv = ldh4(g_h2h + (long long)s * 128 + lane * 4);
        acc.x += hv.x; acc.y += hv.y; acc.z += hv.z; acc.w += hv.w;
    }
    float dd = g_dinv[node];
    int c4 = lane * 4;
    float4 bg = *(const float4*)(b_gcn + c4);
    float4 wv = *(const float4*)(bn_w + c4);
    float4 bv = *(const float4*)(bn_b + c4);
    acc.x = elu(acc.x * dd + bg.x) * wv.x + bv.x;
    acc.y = elu(acc.y * dd + bg.y) * wv.y + bv.y;
    acc.z = elu(acc.z * dd + bg.z) * wv.z + bv.z;
    acc.w = elu(acc.w * dd + bg.w) * wv.w + bv.w;
    *(float4*)(g_out2 + (long long)node * 128 + c4) = acc;

    float4 wg = *(const float4*)(W_gate + c4);
    float p = acc.x * wg.x + acc.y * wg.y + acc.z * wg.z + acc.w * wg.w;
#pragma unroll
    for (int o = 16; o; o >>= 1) p += __shfl_xor_sync(0xffffffffu, p, o);
    if (lane == 0) g_eg[node] = __expf(p + b_gate[0]);
}

__device__ __forceinline__ int lower_bound(const int* __restrict__ batch, int N, int key) {
    int lo = 0, hi = N;
    while (lo < hi) {
        int mid = (lo + hi) >> 1;
        if (__ldg(batch + mid) < key) lo = mid + 1; else hi = mid;
    }
    return lo;
}

// ---------------- pooling + final FC fused; tail re-zeroes g_deg ----------------
__global__ void k_pool_final(const int* __restrict__ batch,
                             const float* __restrict__ W_fc,
                             const float* __restrict__ b_fc,
                             float* __restrict__ out, int N) {
    __shared__ float red[8];
    __shared__ float s_acc[256];
    __shared__ float s_inv;
    int gph = blockIdx.x;
    int t = threadIdx.x;
    int lane = t & 31, wrp = t >> 5;
    int beg = lower_bound(batch, N, gph);
    int end = lower_bound(batch, N, gph + 1);

    float s = 0.f;
    for (int n = beg + t; n < end; n += 256) s += g_eg[n];
#pragma unroll
    for (int o = 16; o; o >>= 1) s += __shfl_xor_sync(0xffffffffu, s, o);
    if (lane == 0) red[wrp] = s;
    __syncthreads();
    if (t == 0) {
        float tot = 0.f;
#pragma unroll
        for (int i = 0; i < 8; i++) tot += red[i];
        s_inv = 1.f / (tot + 1e-16f);
    }
    __syncthreads();
    float inv = s_inv;

    int half = t >> 7, c = t & 127;
    float acc = 0.f;
    int n = beg + half;
    for (; n + 8 <= end; n += 8) {
        acc += g_eg[n + 0] * g_out2[(long long)(n + 0) * 128 + c];
        acc += g_eg[n + 2] * g_out2[(long long)(n + 2) * 128 + c];
        acc += g_eg[n + 4] * g_out2[(long long)(n + 4) * 128 + c];
        acc += g_eg[n + 6] * g_out2[(long long)(n + 6) * 128 + c];
    }
    for (; n < end; n += 2)
        acc += g_eg[n] * g_out2[(long long)n * 128 + c];
    s_acc[t] = acc;
    __syncthreads();

    if (t < 128) {
        float p = (s_acc[t] + s_acc[t + 128]) * inv * W_fc[t];
#pragma unroll
        for (int o = 16; o; o >>= 1) p += __shfl_xor_sync(0xffffffffu, p, o);
        if (lane == 0) red[wrp] = p;
    }
    __syncthreads();
    if (t == 0) out[gph] = red[0] + red[1] + red[2] + red[3] + b_fc[0];

    int gid = gph * 256 + t;
    for (int k = gid; k < NMAX; k += GSEG * 256) g_deg[k] = 0;
}

extern "C" void kernel_launch(void* const* d_in, const int* in_sizes, int n_in,
                              void* d_out, int out_size) {
    const float* x       = (const float*)d_in[0];
    const int*   ei      = (const int*)d_in[1];
    const int*   batch   = (const int*)d_in[2];
    const float* W_gat   = (const float*)d_in[3];
    const float* att_src = (const float*)d_in[4];
    const float* att_dst = (const float*)d_in[5];
    const float* b_gat   = (const float*)d_in[6];
    const float* bn1_w   = (const float*)d_in[7];
    const float* bn1_b   = (const float*)d_in[8];
    const float* W_gcn   = (const float*)d_in[9];
    const float* b_gcn   = (const float*)d_in[10];
    const float* bn2_w   = (const float*)d_in[11];
    const float* bn2_b   = (const float*)d_in[12];
    const float* W_gate  = (const float*)d_in[13];
    const float* b_gate  = (const float*)d_in[14];
    const float* W_fc    = (const float*)d_in[15];
    const float* b_fc    = (const float*)d_in[16];
    float* out = (float*)d_out;

    int N = in_sizes[0] / 128;
    int E = in_sizes[1] / 2;
    if (N > NMAX) N = NMAX;
    if (E > EMAX) E = EMAX;
    int ntiles = (N + STILE - 1) / STILE;

    float *p_out1;
    __half *p_hh, *p_h2h;
    cudaGetSymbolAddress((void**)&p_hh, g_hh);
    cudaGetSymbolAddress((void**)&p_out1, g_out1);
    cudaGetSymbolAddress((void**)&p_h2h, g_h2h);

    int gemm_grid = (N + 127) / 128;

    // CSR build — gemm1 is launch #4 (ncu capture slot)
    k_count<<<(E + 255) / 256, 256>>>(ei, E);
    k_scanA<<<ntiles, 256>>>(N);
    k_scanB<<<1, 64>>>(ntiles, N);
    gemm_f16<0><<<gemm_grid, 256>>>(x, W_gat, p_hh, N, att_src, att_dst);
    k_scanC<<<ntiles, 256>>>(N);
    k_fill<<<(E + 255) / 256, 256>>>(ei, E);

    // GAT aggregation (out1 pre-scaled by dinv)
    k_gat_agg<<<(N * 32 + 255) / 256, 256>>>(b_gat, bn1_w, bn1_b, N);

    // GCN
    gemm_f16<1><<<gemm_grid, 256>>>(p_out1, W_gcn, p_h2h, N, nullptr, nullptr);
    k_gcn_agg<<<(N * 32 + 255) / 256, 256>>>(b_gcn, bn2_w, bn2_b, W_gate, b_gate, N);

    // Pooling + FC (+ deg re-zero)
    k_pool_final<<<GSEG, 256>>>(batch, W_fc, b_fc, out, N);
}